// round 12
// baseline (speedup 1.0000x reference)
#include <cuda_runtime.h>
#include <cstdint>

#define NUM_SEG 100000
#define DIM 32
#define TPB 256
#define ROWS_PER_BLK 256
#define TMA_ROWS 144                           // rows via TMA bulk-reduce
#define RED_ROWS (ROWS_PER_BLK - TMA_ROWS)     // 112 rows via LSU red.global
#define RED_CHUNKS (RED_ROWS * 8)              // 896 float4 chunks
#define TMA_TILE_BYTES (TMA_ROWS * DIM * 4)    // 18 KB

// Scratch: per-segment counts (allocation-free rule => __device__ global)
__device__ float g_counts[NUM_SEG];

__device__ __forceinline__ uint32_t smem_u32(const void* p) {
    uint32_t a;
    asm("{ .reg .u64 t; cvta.to.shared.u64 t, %1; cvt.u32.u64 %0, t; }" : "=r"(a) : "l"(p));
    return a;
}

__device__ __forceinline__ void mbar_wait(uint32_t mb, int parity) {
    asm volatile(
        "{\n\t.reg .pred P;\n"
        "WAIT_%=:\n\t"
        "mbarrier.try_wait.parity.shared.b64 P, [%0], %1, 0x989680;\n\t"
        "@!P bra WAIT_%=;\n\t}"
        :: "r"(mb), "r"(parity) : "memory");
}

// Dual-engine scatter: every CTA routes 56% of its rows through the TMA
// engine (bulk-in + 128B bulk-reduce) and 44% through the LSU (direct
// LDG.128 + red.global.v4, no smem round-trip), so both hardware queues are
// loaded on every SM concurrently. REDG work is issued while the bulk-in is
// in flight.
__global__ void __launch_bounds__(TPB) scatter_kernel(
    const float* __restrict__ x,
    const int* __restrict__ index,
    float* __restrict__ out,
    int nrows)
{
    __shared__ __align__(128) float tile[TMA_ROWS * DIM];  // 18 KB
    __shared__ int segs[ROWS_PER_BLK];
    __shared__ __align__(8) unsigned long long mbar;

    int t = threadIdx.x;
    int row0 = blockIdx.x * ROWS_PER_BLK;
    int row = row0 + t;
    bool full_tile = (row0 + ROWS_PER_BLK) <= nrows;
    uint32_t mb = smem_u32(&mbar);
    const float4* x4 = (const float4*)x;

    if (full_tile) {
        if (t == 0)
            asm volatile("mbarrier.init.shared.b64 [%0], 1;" :: "r"(mb) : "memory");
        __syncthreads();
        if (t == 0) {
            uint32_t dst = smem_u32(tile);
            const float* src = x + (long long)row0 * DIM;
            asm volatile("mbarrier.arrive.expect_tx.shared.b64 _, [%0], %1;"
                         :: "r"(mb), "r"(TMA_TILE_BYTES) : "memory");
            asm volatile(
                "cp.async.bulk.shared::cta.global.mbarrier::complete_tx::bytes "
                "[%0], [%1], %2, [%3];"
                :: "r"(dst), "l"(src), "r"(TMA_TILE_BYTES), "r"(mb) : "memory");
        }

        // Overlap with the in-flight bulk-in: index read + count atomic.
        int seg = index[row];
        if ((unsigned)seg >= NUM_SEG) seg = -1;
        if (seg >= 0) atomicAdd(&g_counts[seg], 1.0f);
        segs[t] = seg;
        __syncthreads();

        // LSU path: rows [TMA_ROWS, 256) straight from global -> red.global.v4.
        // Also overlaps the in-flight bulk-in.
        #pragma unroll
        for (int k = 0; k < 4; k++) {
            int c = t + k * TPB;
            if (c < RED_CHUNKS) {
                int rrow = TMA_ROWS + (c >> 3);
                int s = segs[rrow];
                if (s >= 0) {
                    float4 v = x4[(long long)(row0 + rrow) * 8 + (c & 7)];
                    float* addr = out + (long long)s * DIM + (c & 7) * 4;
                    asm volatile("red.global.add.v4.f32 [%0], {%1, %2, %3, %4};"
                                 :: "l"(addr), "f"(v.x), "f"(v.y), "f"(v.z), "f"(v.w)
                                 : "memory");
                }
            }
        }

        // TMA path: wait for the bulk-in, then 128B bulk-reduce per row.
        mbar_wait(mb, 0);
        if (t < TMA_ROWS && segs[t] >= 0) {
            uint32_t saddr = smem_u32(&tile[t * DIM]);
            float* gdst = out + (long long)segs[t] * DIM;
            asm volatile(
                "cp.reduce.async.bulk.global.shared::cta.bulk_group.add.f32 [%0], [%1], %2;"
                :: "l"(gdst), "r"(saddr), "r"(DIM * 4) : "memory");
        }
    } else {
        // Tail tile: everything via direct LDG + red.global (no smem).
        if (row < nrows) {
            int seg = index[row];
            if ((unsigned)seg < NUM_SEG) {
                atomicAdd(&g_counts[seg], 1.0f);
                #pragma unroll
                for (int q = 0; q < 8; q++) {
                    float4 v = x4[(long long)row * 8 + q];
                    float* addr = out + (long long)seg * DIM + q * 4;
                    asm volatile("red.global.add.v4.f32 [%0], {%1, %2, %3, %4};"
                                 :: "l"(addr), "f"(v.x), "f"(v.y), "f"(v.z), "f"(v.w)
                                 : "memory");
                }
            }
        }
    }
    // Drain bulk ops before CTA exit (smem is read asynchronously).
    asm volatile("cp.async.bulk.commit_group;" ::: "memory");
    asm volatile("cp.async.bulk.wait_group 0;" ::: "memory");
}

// Divide with MLP=4: four independent float4 streams per thread.
__global__ void __launch_bounds__(TPB) divide_kernel(float4* __restrict__ out4, int total4) {
    int base = blockIdx.x * (TPB * 4) + threadIdx.x;
    int i0 = base, i1 = base + TPB, i2 = base + TPB * 2, i3 = base + TPB * 3;

    float4 v0, v1, v2, v3;
    float c0 = 1.f, c1 = 1.f, c2 = 1.f, c3 = 1.f;
    bool b0 = i0 < total4, b1 = i1 < total4, b2 = i2 < total4, b3 = i3 < total4;

    if (b0) { v0 = out4[i0]; c0 = __ldg(&g_counts[i0 >> 3]); }
    if (b1) { v1 = out4[i1]; c1 = __ldg(&g_counts[i1 >> 3]); }
    if (b2) { v2 = out4[i2]; c2 = __ldg(&g_counts[i2 >> 3]); }
    if (b3) { v3 = out4[i3]; c3 = __ldg(&g_counts[i3 >> 3]); }

    if (b0) { float r = __frcp_rn(fmaxf(c0, 1.f)); v0.x*=r; v0.y*=r; v0.z*=r; v0.w*=r; out4[i0]=v0; }
    if (b1) { float r = __frcp_rn(fmaxf(c1, 1.f)); v1.x*=r; v1.y*=r; v1.z*=r; v1.w*=r; out4[i1]=v1; }
    if (b2) { float r = __frcp_rn(fmaxf(c2, 1.f)); v2.x*=r; v2.y*=r; v2.z*=r; v2.w*=r; out4[i2]=v2; }
    if (b3) { float r = __frcp_rn(fmaxf(c3, 1.f)); v3.x*=r; v3.y*=r; v3.z*=r; v3.w*=r; out4[i3]=v3; }
}

extern "C" void kernel_launch(void* const* d_in, const int* in_sizes, int n_in,
                              void* d_out, int out_size) {
    const float* x = (const float*)d_in[0];
    const int* index = (const int*)d_in[1];
    float* out = (float*)d_out;

    int nrows = in_sizes[1];   // 4,000,000
    int total = out_size;      // NUM_SEG * DIM

    void* counts_ptr = nullptr;
    cudaGetSymbolAddress(&counts_ptr, g_counts);
    cudaMemsetAsync(out, 0, (size_t)total * sizeof(float), 0);
    cudaMemsetAsync(counts_ptr, 0, (size_t)NUM_SEG * sizeof(float), 0);

    int sb = (nrows + ROWS_PER_BLK - 1) / ROWS_PER_BLK;
    scatter_kernel<<<sb, TPB>>>(x, index, out, nrows);

    int total4 = total / 4;
    int db = (total4 + TPB * 4 - 1) / (TPB * 4);
    divide_kernel<<<db, TPB>>>((float4*)out, total4);
}